// round 6
// baseline (speedup 1.0000x reference)
#include <cuda_runtime.h>
#include <math.h>
#include <stdint.h>
#include <string.h>

// B=32, T=1024, D_IN=80, enc: 80->512->512->256 (ReLU), F=768, 4H=1024, H=256

// ------------------------- device scratch -------------------------
__device__ float d_h[32768 * 256];
__device__ float d_d1[32768 * 256];
__device__ float d_Z[32768 * 2048];        // [b][t][2048]: cols 0..1023 fwd, 1024..2047 bwd
__device__ float d_biascat[2048];
__device__ uint32_t d_Hc[2][2][32][256];   // [parity][dir][b][k] packed (bf16hi<<16)|bf16lo
__device__ float d_Hout[2][1024][256][32]; // [dir][t][k][b]
__device__ int d_order[32];
__device__ int d_lens[32];
__device__ unsigned d_flags[2][64];
// pre-converted bf16 hi/lo weights + activations
__device__ uint16_t d_Wch[2048 * 768], d_Wcl[2048 * 768];
__device__ uint16_t d_W1h[512 * 512], d_W1l[512 * 512];
__device__ uint16_t d_W2h[256 * 512], d_W2l[256 * 512];
__device__ uint16_t d_A0h[32768 * 512], d_A0l[32768 * 512];
__device__ uint16_t d_A1h[32768 * 512], d_A1l[32768 * 512];
__device__ uint16_t d_Fh[32768 * 768], d_Fl[32768 * 768];

// ------------------------- helpers -------------------------
__device__ __forceinline__ uint32_t s2u(const void* p) {
    uint32_t a;
    asm("{ .reg .u64 t; cvta.to.shared.u64 t, %1; cvt.u32.u64 %0, t; }" : "=r"(a) : "l"(p));
    return a;
}
__device__ __forceinline__ uint32_t cvt2bf(float lo, float hi) {
    uint32_t r;
    asm("cvt.rn.satfinite.bf16x2.f32 %0, %1, %2;" : "=r"(r) : "f"(hi), "f"(lo));
    return r;
}
// pack fp32 -> (bf16hi<<16)|bf16lo
__device__ __forceinline__ uint32_t packhl(float v) {
    uint32_t u = cvt2bf(0.f, v);
    float resid = v - __uint_as_float(u & 0xffff0000u);
    return cvt2bf(resid, v);
}
// pack pair (x0 -> lower bf16, x1 -> upper bf16) + residual pair
__device__ __forceinline__ void pack2(float x0, float x1, uint32_t& ph, uint32_t& pl) {
    ph = cvt2bf(x0, x1);
    float r0 = x0 - __uint_as_float(ph << 16);
    float r1 = x1 - __uint_as_float(ph & 0xffff0000u);
    pl = cvt2bf(r0, r1);
}
__device__ __forceinline__ void ldsm4(uint32_t* r, uint32_t addr) {
    asm volatile("ldmatrix.sync.aligned.m8n8.x4.shared.b16 {%0,%1,%2,%3}, [%4];"
                 : "=r"(r[0]), "=r"(r[1]), "=r"(r[2]), "=r"(r[3]) : "r"(addr));
}
__device__ __forceinline__ void mma16816(float* c, const uint32_t* a, uint32_t b0, uint32_t b1) {
    asm volatile(
        "mma.sync.aligned.m16n8k16.row.col.f32.bf16.bf16.f32 "
        "{%0,%1,%2,%3}, {%4,%5,%6,%7}, {%8,%9}, {%0,%1,%2,%3};"
        : "+f"(c[0]), "+f"(c[1]), "+f"(c[2]), "+f"(c[3])
        : "r"(a[0]), "r"(a[1]), "r"(a[2]), "r"(a[3]), "r"(b0), "r"(b1));
}
#define SWZB(row, c) ((((uint32_t)(row)) << 6) + ((((uint32_t)(c) ^ (((uint32_t)(row) >> 1) & 3))) << 4))

// ------------------------- order (stable argsort desc) + flag reset -------------------------
__global__ void compute_order_k(const int* __restrict__ xlen) {
    int tid = threadIdx.x;
    if (tid < 64) { d_flags[0][tid] = 0u; d_flags[1][tid] = 0u; }
    if (tid == 0) {
        unsigned used = 0;
        for (int p = 0; p < 32; ++p) {
            int best = -1, bl = -2147483647;
            for (int j = 0; j < 32; ++j) {
                if (used & (1u << j)) continue;
                int L = xlen[j];
                if (L > bl) { bl = L; best = j; }
            }
            used |= (1u << best);
            d_order[p] = best;
            d_lens[p] = bl;
        }
    }
}

__global__ void bias_k(const float* __restrict__ bihf, const float* __restrict__ bhhf,
                       const float* __restrict__ bihb, const float* __restrict__ bhhb) {
    int j = blockIdx.x * 1024 + threadIdx.x;
    if (j < 1024) d_biascat[j] = bihf[j] + bhhf[j];
    else d_biascat[j] = bihb[j - 1024] + bhhb[j - 1024];
}

// weight fp32 -> bf16 hi/lo pairs
__global__ void convw_k(const float* __restrict__ src, uint16_t* __restrict__ dh,
                        uint16_t* __restrict__ dl, int npairs) {
    int i = blockIdx.x * 256 + threadIdx.x;
    if (i >= npairs) return;
    float2 v = ((const float2*)src)[i];
    uint32_t ph, pl;
    pack2(v.x, v.y, ph, pl);
    ((uint32_t*)dh)[i] = ph;
    ((uint32_t*)dl)[i] = pl;
}

// ------------------------- fp32 GEMM (K=80 layer 0), outputs bf16 hi/lo -------------------------
__global__ void __launch_bounds__(256) gemm_relu_k(
    const float* __restrict__ A, const float* __restrict__ W,
    const float* __restrict__ bias, uint16_t* __restrict__ Chi, uint16_t* __restrict__ Clo,
    int M, int N, int K) {
    __shared__ float As[8][132];
    __shared__ float Ws[8][132];
    const int tid = threadIdx.x;
    const int n0 = blockIdx.x * 128, m0 = blockIdx.y * 128;
    const int lm = tid >> 1, lq = (tid & 1) * 4;
    const float* arow = A + (size_t)(m0 + lm) * K + lq;
    const float* wrow = W + (size_t)(n0 + lm) * K + lq;
    const int tx = tid & 15, ty = tid >> 4;
    float acc[8][8];
#pragma unroll
    for (int i = 0; i < 8; i++)
#pragma unroll
        for (int j = 0; j < 8; j++) acc[i][j] = 0.f;

    for (int k0 = 0; k0 < K; k0 += 8) {
        float4 av = *(const float4*)(arow + k0);
        float4 wv = *(const float4*)(wrow + k0);
        __syncthreads();
        As[lq + 0][lm] = av.x; As[lq + 1][lm] = av.y;
        As[lq + 2][lm] = av.z; As[lq + 3][lm] = av.w;
        Ws[lq + 0][lm] = wv.x; Ws[lq + 1][lm] = wv.y;
        Ws[lq + 2][lm] = wv.z; Ws[lq + 3][lm] = wv.w;
        __syncthreads();
#pragma unroll
        for (int k = 0; k < 8; k++) {
            float a[8], b[8];
            *(float4*)(a) = *(const float4*)&As[k][ty * 8];
            *(float4*)(a + 4) = *(const float4*)&As[k][ty * 8 + 4];
            *(float4*)(b) = *(const float4*)&Ws[k][tx * 8];
            *(float4*)(b + 4) = *(const float4*)&Ws[k][tx * 8 + 4];
#pragma unroll
            for (int i = 0; i < 8; i++)
#pragma unroll
                for (int j = 0; j < 8; j++) acc[i][j] += a[i] * b[j];
        }
    }
    float bs[8];
    *(float4*)bs = *(const float4*)&bias[n0 + tx * 8];
    *(float4*)(bs + 4) = *(const float4*)&bias[n0 + tx * 8 + 4];
#pragma unroll
    for (int i = 0; i < 8; i++) {
        size_t base = (size_t)(m0 + ty * 8 + i) * N + n0 + tx * 8;
        float v[8];
#pragma unroll
        for (int j = 0; j < 8; j++) v[j] = fmaxf(acc[i][j] + bs[j], 0.f);
        uint4 hv, lv;
        pack2(v[0], v[1], hv.x, lv.x);
        pack2(v[2], v[3], hv.y, lv.y);
        pack2(v[4], v[5], hv.z, lv.z);
        pack2(v[6], v[7], hv.w, lv.w);
        *(uint4*)(Chi + base) = hv;
        *(uint4*)(Clo + base) = lv;
    }
}

// ------------------------- HMMA split-bf16 GEMM (all operands pre-converted) -------------------------
template <int RELU, int OUTBF>
__global__ void __launch_bounds__(256) gemm_mma_k(
    const uint16_t* __restrict__ Ahi, const uint16_t* __restrict__ Alo,
    const uint16_t* __restrict__ Bhi, const uint16_t* __restrict__ Blo,
    const float* __restrict__ bias, float* __restrict__ Cf,
    uint16_t* __restrict__ Chi, uint16_t* __restrict__ Clo,
    int K, int ldo) {
    extern __shared__ char smc[];
    const int tid = threadIdx.x, lane = tid & 31, wid = tid >> 5;
    const int wm = wid >> 2, wn = wid & 3;
    const int n0 = blockIdx.x * 128, m0 = blockIdx.y * 128;
    const int NCH = K >> 5;
    const uint32_t sbase = s2u(smc);
    float* sBias = (float*)(smc + 65536);
    if (tid < 128) sBias[tid] = bias[n0 + tid];

    const int ra = tid >> 2, ca = tid & 3;
    const int ldu = K >> 3;  // uint4 units per row
    const uint4* Ah0 = (const uint4*)Ahi + (size_t)(m0 + ra) * ldu + ca;
    const uint4* Al0 = (const uint4*)Alo + (size_t)(m0 + ra) * ldu + ca;
    const uint4* Ah1 = (const uint4*)Ahi + (size_t)(m0 + 64 + ra) * ldu + ca;
    const uint4* Al1 = (const uint4*)Alo + (size_t)(m0 + 64 + ra) * ldu + ca;
    const uint4* Bh0 = (const uint4*)Bhi + (size_t)(n0 + ra) * ldu + ca;
    const uint4* Bl0 = (const uint4*)Blo + (size_t)(n0 + ra) * ldu + ca;
    const uint4* Bh1 = (const uint4*)Bhi + (size_t)(n0 + 64 + ra) * ldu + ca;
    const uint4* Bl1 = (const uint4*)Blo + (size_t)(n0 + 64 + ra) * ldu + ca;

    float acc[4][4][4];
#pragma unroll
    for (int mi = 0; mi < 4; mi++)
#pragma unroll
        for (int j = 0; j < 4; j++)
#pragma unroll
            for (int q = 0; q < 4; q++) acc[mi][j][q] = 0.f;

    const uint32_t o0 = SWZB(ra, ca), o1 = SWZB(64 + ra, ca);
    {
        char* base = smc;
        *(uint4*)(base + o0) = *Ah0;
        *(uint4*)(base + 8192 + o0) = *Al0;
        *(uint4*)(base + o1) = *Ah1;
        *(uint4*)(base + 8192 + o1) = *Al1;
        *(uint4*)(base + 16384 + o0) = *Bh0;
        *(uint4*)(base + 24576 + o0) = *Bl0;
        *(uint4*)(base + 16384 + o1) = *Bh1;
        *(uint4*)(base + 24576 + o1) = *Bl1;
    }
    __syncthreads();

    for (int i = 0; i < NCH; ++i) {
        uint4 pa0, pa1, pa2, pa3, pb0, pb1, pb2, pb3;
        const bool more = (i + 1 < NCH);
        if (more) {
            const int ku = (i + 1) << 2;
            pa0 = Ah0[ku]; pa1 = Al0[ku]; pa2 = Ah1[ku]; pa3 = Al1[ku];
            pb0 = Bh0[ku]; pb1 = Bl0[ku]; pb2 = Bh1[ku]; pb3 = Bl1[ku];
        }
        const uint32_t ab = sbase + (i & 1) * 32768;
        const uint32_t bb = ab + 16384;
#pragma unroll
        for (int ks = 0; ks < 2; ++ks) {
            const int r = lane & 15;
            const int cu = (ks << 1) + (lane >> 4);
            uint32_t ah[4][4], al[4][4], bh[2][4], bl[2][4];
#pragma unroll
            for (int mi = 0; mi < 4; ++mi) {
                uint32_t off = SWZB(wm * 64 + mi * 16 + r, cu);
                ldsm4(ah[mi], ab + off);
                ldsm4(al[mi], ab + 8192 + off);
            }
#pragma unroll
            for (int ni = 0; ni < 2; ++ni) {
                uint32_t off = SWZB(wn * 32 + ni * 16 + r, cu);
                ldsm4(bh[ni], bb + off);
                ldsm4(bl[ni], bb + 8192 + off);
            }
#pragma unroll
            for (int mi = 0; mi < 4; ++mi)
#pragma unroll
                for (int j = 0; j < 4; ++j) {
                    const int ni = j >> 1, s = j & 1;
                    mma16816(acc[mi][j], ah[mi], bh[ni][s], bh[ni][s + 2]);
                    mma16816(acc[mi][j], al[mi], bh[ni][s], bh[ni][s + 2]);
                    mma16816(acc[mi][j], ah[mi], bl[ni][s], bl[ni][s + 2]);
                }
        }
        if (more) {
            char* base = smc + ((i + 1) & 1) * 32768;
            *(uint4*)(base + o0) = pa0;
            *(uint4*)(base + 8192 + o0) = pa1;
            *(uint4*)(base + o1) = pa2;
            *(uint4*)(base + 8192 + o1) = pa3;
            *(uint4*)(base + 16384 + o0) = pb0;
            *(uint4*)(base + 24576 + o0) = pb1;
            *(uint4*)(base + 16384 + o1) = pb2;
            *(uint4*)(base + 24576 + o1) = pb3;
        }
        __syncthreads();
    }

#pragma unroll
    for (int mi = 0; mi < 4; ++mi)
#pragma unroll
        for (int j = 0; j < 4; ++j) {
            const int row = m0 + wm * 64 + mi * 16 + (lane >> 2);
            const int colL = wn * 32 + j * 8 + (lane & 3) * 2;
            const float b0v = sBias[colL], b1v = sBias[colL + 1];
            float x0 = acc[mi][j][0] + b0v, x1 = acc[mi][j][1] + b1v;
            float x2 = acc[mi][j][2] + b0v, x3 = acc[mi][j][3] + b1v;
            if (RELU) {
                x0 = fmaxf(x0, 0.f); x1 = fmaxf(x1, 0.f);
                x2 = fmaxf(x2, 0.f); x3 = fmaxf(x3, 0.f);
            }
            if (OUTBF) {
                uint32_t ph, pl;
                pack2(x0, x1, ph, pl);
                *(uint32_t*)(Chi + (size_t)row * ldo + n0 + colL) = ph;
                *(uint32_t*)(Clo + (size_t)row * ldo + n0 + colL) = pl;
                pack2(x2, x3, ph, pl);
                *(uint32_t*)(Chi + (size_t)(row + 8) * ldo + n0 + colL) = ph;
                *(uint32_t*)(Clo + (size_t)(row + 8) * ldo + n0 + colL) = pl;
            } else {
                *(float2*)(Cf + (size_t)row * ldo + n0 + colL) = make_float2(x0, x1);
                *(float2*)(Cf + (size_t)(row + 8) * ldo + n0 + colL) = make_float2(x2, x3);
            }
        }
}

// ------------------------- deltas (WIN=2, edge replicate) -------------------------
__global__ void deltas_k() {
    int idx = blockIdx.x * 256 + threadIdx.x;
    if (idx >= 32 * 1024 * 64) return;
    int c4 = idx & 63, t = (idx >> 6) & 1023, b = idx >> 16;
    const float4* h4 = (const float4*)d_h;
    size_t base = (size_t)b * 65536;
    int tp1 = min(t + 1, 1023), tm1 = max(t - 1, 0);
    int tp2 = min(t + 2, 1023), tm2 = max(t - 2, 0);
    float4 a = h4[base + (size_t)tp1 * 64 + c4];
    float4 bb = h4[base + (size_t)tm1 * 64 + c4];
    float4 c = h4[base + (size_t)tp2 * 64 + c4];
    float4 d = h4[base + (size_t)tm2 * 64 + c4];
    float4 z;
    z.x = (a.x - bb.x) * 0.5f + (c.x - d.x) * 0.25f;
    z.y = (a.y - bb.y) * 0.5f + (c.y - d.y) * 0.25f;
    z.z = (a.z - bb.z) * 0.5f + (c.z - d.z) * 0.25f;
    z.w = (a.w - bb.w) * 0.5f + (c.w - d.w) * 0.25f;
    ((float4*)d_d1)[base + (size_t)t * 64 + c4] = z;
}

// ------------------------- feat assembly (sorted) -> bf16 hi/lo -------------------------
__global__ void feat_k() {
    int idx = blockIdx.x * 256 + threadIdx.x;
    if (idx >= 32 * 1024 * 64) return;
    int c4 = idx & 63, t = (idx >> 6) & 1023, sb = idx >> 16;
    int b = d_order[sb];
    const float4* h4 = (const float4*)d_h;
    const float4* d14 = (const float4*)d_d1;
    size_t base = (size_t)b * 65536;
    size_t srow = base + (size_t)t * 64 + c4;
    float4 hv = h4[srow];
    float4 d1v = d14[srow];
    int tp1 = min(t + 1, 1023), tm1 = max(t - 1, 0);
    int tp2 = min(t + 2, 1023), tm2 = max(t - 2, 0);
    float4 a = d14[base + (size_t)tp1 * 64 + c4];
    float4 bb = d14[base + (size_t)tm1 * 64 + c4];
    float4 c = d14[base + (size_t)tp2 * 64 + c4];
    float4 d = d14[base + (size_t)tm2 * 64 + c4];
    float4 d2v;
    d2v.x = (a.x - bb.x) * 0.5f + (c.x - d.x) * 0.25f;
    d2v.y = (a.y - bb.y) * 0.5f + (c.y - d.y) * 0.25f;
    d2v.z = (a.z - bb.z) * 0.5f + (c.z - d.z) * 0.25f;
    d2v.w = (a.w - bb.w) * 0.5f + (c.w - d.w) * 0.25f;
    uint32_t* Fh32 = (uint32_t*)d_Fh;
    uint32_t* Fl32 = (uint32_t*)d_Fl;
    size_t ob = ((size_t)sb * 1024 + t) * 384;  // pairs per row = 768/2
    uint2 hp, lp;
    pack2(hv.x, hv.y, hp.x, lp.x);
    pack2(hv.z, hv.w, hp.y, lp.y);
    *(uint2*)&Fh32[ob + c4 * 2] = hp;
    *(uint2*)&Fl32[ob + c4 * 2] = lp;
    pack2(d1v.x, d1v.y, hp.x, lp.x);
    pack2(d1v.z, d1v.w, hp.y, lp.y);
    *(uint2*)&Fh32[ob + 128 + c4 * 2] = hp;
    *(uint2*)&Fl32[ob + 128 + c4 * 2] = lp;
    pack2(d2v.x, d2v.y, hp.x, lp.x);
    pack2(d2v.z, d2v.w, hp.y, lp.y);
    *(uint2*)&Fh32[ob + 256 + c4 * 2] = hp;
    *(uint2*)&Fl32[ob + 256 + c4 * 2] = lp;
}

// ------------------------- persistent bidirectional LSTM recurrence (HMMA) -------------------------
__global__ void __launch_bounds__(256, 1) lstm_rec_k(
    const float* __restrict__ Whh_f, const float* __restrict__ Whh_b,
    const float* __restrict__ h0, const float* __restrict__ c0) {
    extern __shared__ char smc[];
    const int AHOF = 0, ALOF = 16384, BHOF = 32768, BLOF = 40960, POFF = 49152;
    float* P = (float*)(smc + POFF);
    const uint32_t sb = s2u(smc);
    const int tid = threadIdx.x, lane = tid & 31, wid = tid >> 5;
    const int dir = blockIdx.x >> 6, slice = blockIdx.x & 63;
    const float* Whh = dir ? Whh_b : Whh_f;

    // stage W slice (16 rows x 256 k) as bf16 hi/lo, ldmatrix layout
    for (int i = tid; i < 4096; i += 256) {
        int r = i >> 8, k = i & 255;
        int grow = ((r >> 2) << 8) + (slice << 2) + (r & 3);
        float w = __ldg(Whh + (size_t)grow * 256 + k);
        uint32_t pk = packhl(w);
        int c = k >> 3;
        int phys = (c & 24) | ((c ^ r) & 7);
        int off = r * 512 + phys * 16 + (k & 7) * 2;
        *(uint16_t*)(smc + BHOF + off) = (uint16_t)(pk >> 16);
        *(uint16_t*)(smc + BLOF + off) = (uint16_t)(pk & 0xffffu);
    }

    const int uq = tid >> 5, ub = tid & 31;
    const int kidx = (slice << 2) + uq;
    float creg = 0.f;
    int Lb = 0;
    if (tid < 128) {
        creg = c0[(dir * 32 + ub) * 256 + kidx];
        d_Hc[0][dir][ub][kidx] = packhl(h0[(dir * 32 + ub) * 256 + kidx]);
        Lb = d_lens[ub];
    }
    __syncthreads();
    if (tid == 0)
        asm volatile("st.release.gpu.global.u32 [%0], %1;"
                     :: "l"(&d_flags[dir][slice]), "r"(1u) : "memory");

    const int rr = lane & 15, hs = lane >> 4;

    for (int t = 0; t < 1024; ++t) {
        // Z load first: latency overlaps the flag spin
        float zreg[4];
        if (tid < 128) {
            int tt = dir ? max(Lb - 1 - t, 0) : t;
            const float* zp = d_Z + ((size_t)ub * 1024 + tt) * 2048 + dir * 1024 + (slice << 2) + uq;
#pragma unroll
            for (int g = 0; g < 4; ++g) zreg[g] = __ldg(zp + (g << 8));
        }
        // warp 0: wait for all 64 CTAs of this dir to have posted step t+1
        if (wid == 0) {
            const unsigned tgt = (unsigned)(t + 1);
            const unsigned* fl = &d_flags[dir][0];
            bool ok;
            do {
                unsigned v0, v1;
                asm volatile("ld.acquire.gpu.global.u32 %0, [%1];"
                             : "=r"(v0) : "l"(fl + lane) : "memory");
                asm volatile("ld.acquire.gpu.global.u32 %0, [%1];"
                             : "=r"(v1) : "l"(fl + lane + 32) : "memory");
                ok = (v0 >= tgt) && (v1 >= tgt);
            } while (!__all_sync(0xffffffffu, ok));
        }
        __syncthreads();
        // stage h(t): packed global -> smem bf16 hi/lo (ldmatrix layout)
        {
            const uint4* src = (const uint4*)&d_Hc[t & 1][dir][0][0];
#pragma unroll
            for (int q = 0; q < 4; ++q) {
                int p = q * 256 + tid;
                int b = p >> 5, c = p & 31;
                uint4 v0 = __ldcg(src + p * 2);
                uint4 v1 = __ldcg(src + p * 2 + 1);
                uint4 hiu, lou;
                hiu.x = __byte_perm(v0.x, v0.y, 0x7632);
                hiu.y = __byte_perm(v0.z, v0.w, 0x7632);
                hiu.z = __byte_perm(v1.x, v1.y, 0x7632);
                hiu.w = __byte_perm(v1.z, v1.w, 0x7632);
                lou.x = __byte_perm(v0.x, v0.y, 0x5410);
                lou.y = __byte_perm(v0.z, v0.w, 0x5410);
                lou.z = __byte_perm(v1.x, v1.y, 0x5410);
                lou.w = __byte_perm(v1.z, v1.w, 0x5410);
                int phys = (c & 24) | ((c ^ b) & 7);
                int off = b * 512 + phys * 16;
                *(uint4*)(smc + AHOF + off) = hiu;
                *(uint4*)(smc + ALOF + off) = lou;
            }
        }
        __syncthreads();
        // mma: warp wid owns k chunk wid*32
        float acc[2][2][4];
#pragma unroll
        for (int a = 0; a < 2; a++)
#pragma unroll
            for (int bq = 0; bq < 2; bq++)
#pragma unroll
                for (int q2 = 0; q2 < 4; q2++) acc[a][bq][q2] = 0.f;
        uint32_t ahr[2][2][4], alr[2][2][4], bhr[2][4], blr[2][4];
#pragma unroll
        for (int kt = 0; kt < 2; ++kt) {
            int cu = wid * 4 + kt * 2 + hs;
#pragma unroll
            for (int mt = 0; mt < 2; ++mt) {
                int row = mt * 16 + rr;
                int phys = (cu & 24) | ((cu ^ row) & 7);
                uint32_t off = (uint32_t)(row * 512 + phys * 16);
                ldsm4(ahr[mt][kt], sb + AHOF + off);
                ldsm4(alr[mt][kt], sb + ALOF + off);
            }
            {
                int row = rr;
                int phys = (cu & 24) | ((cu ^ row) & 7);
                uint32_t off = (uint32_t)(row * 512 + phys * 16);
                ldsm4(bhr[kt], sb + BHOF + off);
                ldsm4(blr[kt], sb + BLOF + off);
            }
        }
#pragma unroll
        for (int mt = 0; mt < 2; ++mt)
#pragma unroll
            for (int nt = 0; nt < 2; ++nt)
#pragma unroll
                for (int kt = 0; kt < 2; ++kt) {
                    mma16816(acc[mt][nt], ahr[mt][kt], bhr[kt][nt], bhr[kt][nt + 2]);
                    mma16816(acc[mt][nt], alr[mt][kt], bhr[kt][nt], bhr[kt][nt + 2]);
                    mma16816(acc[mt][nt], ahr[mt][kt], blr[kt][nt], blr[kt][nt + 2]);
                }
#pragma unroll
        for (int mt = 0; mt < 2; ++mt)
#pragma unroll
            for (int nt = 0; nt < 2; ++nt) {
                int b = mt * 16 + (lane >> 2);
                int r = nt * 8 + (lane & 3) * 2;
                P[(wid * 32 + b) * 17 + r] = acc[mt][nt][0];
                P[(wid * 32 + b) * 17 + r + 1] = acc[mt][nt][1];
                P[(wid * 32 + b + 8) * 17 + r] = acc[mt][nt][2];
                P[(wid * 32 + b + 8) * 17 + r + 1] = acc[mt][nt][3];
            }
        __syncthreads();
        if (tid < 128) {
            float g4[4];
#pragma unroll
            for (int g = 0; g < 4; ++g) {
                float s = zreg[g];
                int ri = 4 * g + uq;
#pragma unroll
                for (int w8 = 0; w8 < 8; ++w8) s += P[(w8 * 32 + ub) * 17 + ri];
                g4[g] = s;
            }
            float is = 1.f / (1.f + expf(-g4[0]));
            float fs = 1.f / (1.f + expf(-g4[1]));
            float gt = tanhf(g4[2]);
            float os = 1.f / (1.f + expf(-g4[3]));
            creg = fs * creg + is * gt;
            float hv = os * tanhf(creg);
            d_Hout[dir][t][kidx][ub] = hv;
            d_Hc[(t + 1) & 1][dir][ub][kidx] = packhl(hv);
        }
        __syncthreads();
        if (tid == 0)
            asm volatile("st.release.gpu.global.u32 [%0], %1;"
                         :: "l"(&d_flags[dir][slice]), "r"((unsigned)(t + 2)) : "memory");
    }
}

// ------------------------- output assembly -------------------------
__global__ void outk(float* __restrict__ out, int out_size) {
    int idx = blockIdx.x * 256 + threadIdx.x;
    if (idx >= out_size) return;
    if (idx < 16777216) {
        int j = idx & 511;
        int t = (idx >> 9) & 1023;
        int sb = idx >> 19;
        int L = d_lens[sb];
        float v = 0.f;
        if (t < L) {
            if (j < 256) v = d_Hout[0][t][j][sb];
            else v = d_Hout[1][L - 1 - t][j - 256][sb];
        }
        out[idx] = v;
    } else {
        int k = idx - 16777216;
        if (k < 32) out[idx] = (float)d_order[k];
        else out[idx] = 0.f;
    }
}

// ------------------------- launch -------------------------
extern "C" void kernel_launch(void* const* d_in, const int* in_sizes, int n_in,
                              void* d_out, int out_size) {
    const float* x = (const float*)d_in[0];
    const int* xlen = (const int*)d_in[1];
    const float* W0 = (const float*)d_in[2];
    const float* b0 = (const float*)d_in[3];
    const float* W1 = (const float*)d_in[4];
    const float* b1 = (const float*)d_in[5];
    const float* W2 = (const float*)d_in[6];
    const float* b2 = (const float*)d_in[7];
    const float* Wih_f = (const float*)d_in[8];
    const float* Whh_f = (const float*)d_in[9];
    const float* bih_f = (const float*)d_in[10];
    const float* bhh_f = (const float*)d_in[11];
    const float* Wih_b = (const float*)d_in[12];
    const float* Whh_b = (const float*)d_in[13];
    const float* bih_b = (const float*)d_in[14];
    const float* bhh_b = (const float*)d_in[15];
    const float* h0 = (const float*)d_in[16];
    const float* c0 = (const float*)d_in[17];
    float* out = (float*)d_out;

    void *p_h, *p_Z, *p_bias;
    void *p_wch, *p_wcl, *p_w1h, *p_w1l, *p_w2h, *p_w2l;
    void *p_a0h, *p_a0l, *p_a1h, *p_a1l, *p_fh, *p_fl;
    cudaGetSymbolAddress(&p_h, d_h);
    cudaGetSymbolAddress(&p_Z, d_Z);
    cudaGetSymbolAddress(&p_bias, d_biascat);
    cudaGetSymbolAddress(&p_wch, d_Wch);
    cudaGetSymbolAddress(&p_wcl, d_Wcl);
    cudaGetSymbolAddress(&p_w1h, d_W1h);
    cudaGetSymbolAddress(&p_w1l, d_W1l);
    cudaGetSymbolAddress(&p_w2h, d_W2h);
    cudaGetSymbolAddress(&p_w2l, d_W2l);
    cudaGetSymbolAddress(&p_a0h, d_A0h);
    cudaGetSymbolAddress(&p_a0l, d_A0l);
    cudaGetSymbolAddress(&p_a1h, d_A1h);
    cudaGetSymbolAddress(&p_a1l, d_A1l);
    cudaGetSymbolAddress(&p_fh, d_Fh);
    cudaGetSymbolAddress(&p_fl, d_Fl);

    cudaFuncSetAttribute(gemm_mma_k<0, 0>, cudaFuncAttributeMaxDynamicSharedMemorySize, 66048);
    cudaFuncSetAttribute(gemm_mma_k<1, 0>, cudaFuncAttributeMaxDynamicSharedMemorySize, 66048);
    cudaFuncSetAttribute(gemm_mma_k<1, 1>, cudaFuncAttributeMaxDynamicSharedMemorySize, 66048);
    cudaFuncSetAttribute(lstm_rec_k, cudaFuncAttributeMaxDynamicSharedMemorySize, 66560);

    compute_order_k<<<1, 64>>>(xlen);
    bias_k<<<2, 1024>>>(bih_f, bhh_f, bih_b, bhh_b);

    // pre-convert static weights to bf16 hi/lo
    convw_k<<<(131072 + 255) / 256, 256>>>(W1, (uint16_t*)p_w1h, (uint16_t*)p_w1l, 131072);
    convw_k<<<(65536 + 255) / 256, 256>>>(W2, (uint16_t*)p_w2h, (uint16_t*)p_w2l, 65536);
    convw_k<<<(393216 + 255) / 256, 256>>>(Wih_f, (uint16_t*)p_wch, (uint16_t*)p_wcl, 393216);
    convw_k<<<(393216 + 255) / 256, 256>>>(
        Wih_b, (uint16_t*)p_wch + 1024 * 768, (uint16_t*)p_wcl + 1024 * 768, 393216);

    // encoder (activations flow as bf16 hi/lo)
    gemm_relu_k<<<dim3(4, 256), 256>>>(x, W0, b0, (uint16_t*)p_a0h, (uint16_t*)p_a0l,
                                       32768, 512, 80);
    gemm_mma_k<1, 1><<<dim3(4, 256), 256, 66048>>>(
        (const uint16_t*)p_a0h, (const uint16_t*)p_a0l,
        (const uint16_t*)p_w1h, (const uint16_t*)p_w1l,
        b1, nullptr, (uint16_t*)p_a1h, (uint16_t*)p_a1l, 512, 512);
    gemm_mma_k<1, 0><<<dim3(2, 256), 256, 66048>>>(
        (const uint16_t*)p_a1h, (const uint16_t*)p_a1l,
        (const uint16_t*)p_w2h, (const uint16_t*)p_w2l,
        b2, (float*)p_h, nullptr, nullptr, 512, 256);

    deltas_k<<<8192, 256>>>();
    feat_k<<<8192, 256>>>();

    // Z = feat @ [Wih_f ; Wih_b]^T + biascat
    gemm_mma_k<0, 0><<<dim3(16, 256), 256, 66048>>>(
        (const uint16_t*)p_fh, (const uint16_t*)p_fl,
        (const uint16_t*)p_wch, (const uint16_t*)p_wcl,
        (const float*)p_bias, (float*)p_Z, nullptr, nullptr, 768, 2048);

    lstm_rec_k<<<128, 256, 66560>>>(Whh_f, Whh_b, h0, c0);

    outk<<<(out_size + 255) / 256, 256>>>(out, out_size);
}

// round 7
// speedup vs baseline: 1.2380x; 1.2380x over previous
#include <cuda_runtime.h>
#include <math.h>
#include <stdint.h>
#include <string.h>

// B=32, T=1024, D_IN=80, enc: 80->512->512->256 (ReLU), F=768, 4H=1024, H=256

// ------------------------- device scratch -------------------------
__device__ float d_h[32768 * 256];
__device__ float d_d1[32768 * 256];
__device__ float d_Z[32768 * 2048];        // [b][t][2048]: cols 0..1023 fwd, 1024..2047 bwd
__device__ float d_biascat[2048];
__device__ uint32_t d_Hc[2][2][32][256];   // [parity][dir][b][k] packed (bf16hi<<16)|bf16lo
__device__ float d_Hout[2][1024][256][32]; // [dir][t][k][b]
__device__ int d_order[32];
__device__ int d_lens[32];
__device__ unsigned d_ctr2[2];
// pre-converted bf16 hi/lo weights + activations
__device__ uint16_t d_Wch[2048 * 768], d_Wcl[2048 * 768];
__device__ uint16_t d_W1h[512 * 512], d_W1l[512 * 512];
__device__ uint16_t d_W2h[256 * 512], d_W2l[256 * 512];
__device__ uint16_t d_A0h[32768 * 512], d_A0l[32768 * 512];
__device__ uint16_t d_A1h[32768 * 512], d_A1l[32768 * 512];
__device__ uint16_t d_Fh[32768 * 768], d_Fl[32768 * 768];

// ------------------------- helpers -------------------------
__device__ __forceinline__ uint32_t s2u(const void* p) {
    uint32_t a;
    asm("{ .reg .u64 t; cvta.to.shared.u64 t, %1; cvt.u32.u64 %0, t; }" : "=r"(a) : "l"(p));
    return a;
}
__device__ __forceinline__ uint32_t cvt2bf(float lo, float hi) {
    uint32_t r;
    asm("cvt.rn.satfinite.bf16x2.f32 %0, %1, %2;" : "=r"(r) : "f"(hi), "f"(lo));
    return r;
}
__device__ __forceinline__ uint32_t packhl(float v) {
    uint32_t u = cvt2bf(0.f, v);
    float resid = v - __uint_as_float(u & 0xffff0000u);
    return cvt2bf(resid, v);
}
__device__ __forceinline__ void pack2(float x0, float x1, uint32_t& ph, uint32_t& pl) {
    ph = cvt2bf(x0, x1);
    float r0 = x0 - __uint_as_float(ph << 16);
    float r1 = x1 - __uint_as_float(ph & 0xffff0000u);
    pl = cvt2bf(r0, r1);
}
__device__ __forceinline__ void ldsm4(uint32_t* r, uint32_t addr) {
    asm volatile("ldmatrix.sync.aligned.m8n8.x4.shared.b16 {%0,%1,%2,%3}, [%4];"
                 : "=r"(r[0]), "=r"(r[1]), "=r"(r[2]), "=r"(r[3]) : "r"(addr));
}
__device__ __forceinline__ void mma16816(float* c, const uint32_t* a, uint32_t b0, uint32_t b1) {
    asm volatile(
        "mma.sync.aligned.m16n8k16.row.col.f32.bf16.bf16.f32 "
        "{%0,%1,%2,%3}, {%4,%5,%6,%7}, {%8,%9}, {%0,%1,%2,%3};"
        : "+f"(c[0]), "+f"(c[1]), "+f"(c[2]), "+f"(c[3])
        : "r"(a[0]), "r"(a[1]), "r"(a[2]), "r"(a[3]), "r"(b0), "r"(b1));
}
#define SWZB(row, c) ((((uint32_t)(row)) << 6) + ((((uint32_t)(c) ^ (((uint32_t)(row) >> 1) & 3))) << 4))

// ------------------------- order (stable argsort desc) + ctr reset -------------------------
__global__ void compute_order_k(const int* __restrict__ xlen) {
    if (threadIdx.x == 0) {
        unsigned used = 0;
        for (int p = 0; p < 32; ++p) {
            int best = -1, bl = -2147483647;
            for (int j = 0; j < 32; ++j) {
                if (used & (1u << j)) continue;
                int L = xlen[j];
                if (L > bl) { bl = L; best = j; }
            }
            used |= (1u << best);
            d_order[p] = best;
            d_lens[p] = bl;
        }
        d_ctr2[0] = 0u;
        d_ctr2[1] = 0u;
    }
}

__global__ void bias_k(const float* __restrict__ bihf, const float* __restrict__ bhhf,
                       const float* __restrict__ bihb, const float* __restrict__ bhhb) {
    int j = blockIdx.x * 1024 + threadIdx.x;
    if (j < 1024) d_biascat[j] = bihf[j] + bhhf[j];
    else d_biascat[j] = bihb[j - 1024] + bhhb[j - 1024];
}

// weight fp32 -> bf16 hi/lo pairs
__global__ void convw_k(const float* __restrict__ src, uint16_t* __restrict__ dh,
                        uint16_t* __restrict__ dl, int npairs) {
    int i = blockIdx.x * 256 + threadIdx.x;
    if (i >= npairs) return;
    float2 v = ((const float2*)src)[i];
    uint32_t ph, pl;
    pack2(v.x, v.y, ph, pl);
    ((uint32_t*)dh)[i] = ph;
    ((uint32_t*)dl)[i] = pl;
}

// ------------------------- fp32 GEMM (K=80 layer 0), outputs bf16 hi/lo -------------------------
__global__ void __launch_bounds__(256) gemm_relu_k(
    const float* __restrict__ A, const float* __restrict__ W,
    const float* __restrict__ bias, uint16_t* __restrict__ Chi, uint16_t* __restrict__ Clo,
    int M, int N, int K) {
    __shared__ float As[8][132];
    __shared__ float Ws[8][132];
    const int tid = threadIdx.x;
    const int n0 = blockIdx.x * 128, m0 = blockIdx.y * 128;
    const int lm = tid >> 1, lq = (tid & 1) * 4;
    const float* arow = A + (size_t)(m0 + lm) * K + lq;
    const float* wrow = W + (size_t)(n0 + lm) * K + lq;
    const int tx = tid & 15, ty = tid >> 4;
    float acc[8][8];
#pragma unroll
    for (int i = 0; i < 8; i++)
#pragma unroll
        for (int j = 0; j < 8; j++) acc[i][j] = 0.f;

    for (int k0 = 0; k0 < K; k0 += 8) {
        float4 av = *(const float4*)(arow + k0);
        float4 wv = *(const float4*)(wrow + k0);
        __syncthreads();
        As[lq + 0][lm] = av.x; As[lq + 1][lm] = av.y;
        As[lq + 2][lm] = av.z; As[lq + 3][lm] = av.w;
        Ws[lq + 0][lm] = wv.x; Ws[lq + 1][lm] = wv.y;
        Ws[lq + 2][lm] = wv.z; Ws[lq + 3][lm] = wv.w;
        __syncthreads();
#pragma unroll
        for (int k = 0; k < 8; k++) {
            float a[8], b[8];
            *(float4*)(a) = *(const float4*)&As[k][ty * 8];
            *(float4*)(a + 4) = *(const float4*)&As[k][ty * 8 + 4];
            *(float4*)(b) = *(const float4*)&Ws[k][tx * 8];
            *(float4*)(b + 4) = *(const float4*)&Ws[k][tx * 8 + 4];
#pragma unroll
            for (int i = 0; i < 8; i++)
#pragma unroll
                for (int j = 0; j < 8; j++) acc[i][j] += a[i] * b[j];
        }
    }
    float bs[8];
    *(float4*)bs = *(const float4*)&bias[n0 + tx * 8];
    *(float4*)(bs + 4) = *(const float4*)&bias[n0 + tx * 8 + 4];
#pragma unroll
    for (int i = 0; i < 8; i++) {
        size_t base = (size_t)(m0 + ty * 8 + i) * N + n0 + tx * 8;
        float v[8];
#pragma unroll
        for (int j = 0; j < 8; j++) v[j] = fmaxf(acc[i][j] + bs[j], 0.f);
        uint4 hv, lv;
        pack2(v[0], v[1], hv.x, lv.x);
        pack2(v[2], v[3], hv.y, lv.y);
        pack2(v[4], v[5], hv.z, lv.z);
        pack2(v[6], v[7], hv.w, lv.w);
        *(uint4*)(Chi + base) = hv;
        *(uint4*)(Clo + base) = lv;
    }
}

// ------------------------- HMMA split-bf16 GEMM (all operands pre-converted) -------------------------
template <int RELU, int OUTBF>
__global__ void __launch_bounds__(256) gemm_mma_k(
    const uint16_t* __restrict__ Ahi, const uint16_t* __restrict__ Alo,
    const uint16_t* __restrict__ Bhi, const uint16_t* __restrict__ Blo,
    const float* __restrict__ bias, float* __restrict__ Cf,
    uint16_t* __restrict__ Chi, uint16_t* __restrict__ Clo,
    int K, int ldo) {
    extern __shared__ char smc[];
    const int tid = threadIdx.x, lane = tid & 31, wid = tid >> 5;
    const int wm = wid >> 2, wn = wid & 3;
    const int n0 = blockIdx.x * 128, m0 = blockIdx.y * 128;
    const int NCH = K >> 5;
    const uint32_t sbase = s2u(smc);
    float* sBias = (float*)(smc + 65536);
    if (tid < 128) sBias[tid] = bias[n0 + tid];

    const int ra = tid >> 2, ca = tid & 3;
    const int ldu = K >> 3;
    const uint4* Ah0 = (const uint4*)Ahi + (size_t)(m0 + ra) * ldu + ca;
    const uint4* Al0 = (const uint4*)Alo + (size_t)(m0 + ra) * ldu + ca;
    const uint4* Ah1 = (const uint4*)Ahi + (size_t)(m0 + 64 + ra) * ldu + ca;
    const uint4* Al1 = (const uint4*)Alo + (size_t)(m0 + 64 + ra) * ldu + ca;
    const uint4* Bh0 = (const uint4*)Bhi + (size_t)(n0 + ra) * ldu + ca;
    const uint4* Bl0 = (const uint4*)Blo + (size_t)(n0 + ra) * ldu + ca;
    const uint4* Bh1 = (const uint4*)Bhi + (size_t)(n0 + 64 + ra) * ldu + ca;
    const uint4* Bl1 = (const uint4*)Blo + (size_t)(n0 + 64 + ra) * ldu + ca;

    float acc[4][4][4];
#pragma unroll
    for (int mi = 0; mi < 4; mi++)
#pragma unroll
        for (int j = 0; j < 4; j++)
#pragma unroll
            for (int q = 0; q < 4; q++) acc[mi][j][q] = 0.f;

    const uint32_t o0 = SWZB(ra, ca), o1 = SWZB(64 + ra, ca);
    {
        char* base = smc;
        *(uint4*)(base + o0) = *Ah0;
        *(uint4*)(base + 8192 + o0) = *Al0;
        *(uint4*)(base + o1) = *Ah1;
        *(uint4*)(base + 8192 + o1) = *Al1;
        *(uint4*)(base + 16384 + o0) = *Bh0;
        *(uint4*)(base + 24576 + o0) = *Bl0;
        *(uint4*)(base + 16384 + o1) = *Bh1;
        *(uint4*)(base + 24576 + o1) = *Bl1;
    }
    __syncthreads();

    for (int i = 0; i < NCH; ++i) {
        uint4 pa0, pa1, pa2, pa3, pb0, pb1, pb2, pb3;
        const bool more = (i + 1 < NCH);
        if (more) {
            const int ku = (i + 1) << 2;
            pa0 = Ah0[ku]; pa1 = Al0[ku]; pa2 = Ah1[ku]; pa3 = Al1[ku];
            pb0 = Bh0[ku]; pb1 = Bl0[ku]; pb2 = Bh1[ku]; pb3 = Bl1[ku];
        }
        const uint32_t ab = sbase + (i & 1) * 32768;
        const uint32_t bb = ab + 16384;
#pragma unroll
        for (int ks = 0; ks < 2; ++ks) {
            const int r = lane & 15;
            const int cu = (ks << 1) + (lane >> 4);
            uint32_t ah[4][4], al[4][4], bh[2][4], bl[2][4];
#pragma unroll
            for (int mi = 0; mi < 4; ++mi) {
                uint32_t off = SWZB(wm * 64 + mi * 16 + r, cu);
                ldsm4(ah[mi], ab + off);
                ldsm4(al[mi], ab + 8192 + off);
            }
#pragma unroll
            for (int ni = 0; ni < 2; ++ni) {
                uint32_t off = SWZB(wn * 32 + ni * 16 + r, cu);
                ldsm4(bh[ni], bb + off);
                ldsm4(bl[ni], bb + 8192 + off);
            }
#pragma unroll
            for (int mi = 0; mi < 4; ++mi)
#pragma unroll
                for (int j = 0; j < 4; ++j) {
                    const int ni = j >> 1, s = j & 1;
                    mma16816(acc[mi][j], ah[mi], bh[ni][s], bh[ni][s + 2]);
                    mma16816(acc[mi][j], al[mi], bh[ni][s], bh[ni][s + 2]);
                    mma16816(acc[mi][j], ah[mi], bl[ni][s], bl[ni][s + 2]);
                }
        }
        if (more) {
            char* base = smc + ((i + 1) & 1) * 32768;
            *(uint4*)(base + o0) = pa0;
            *(uint4*)(base + 8192 + o0) = pa1;
            *(uint4*)(base + o1) = pa2;
            *(uint4*)(base + 8192 + o1) = pa3;
            *(uint4*)(base + 16384 + o0) = pb0;
            *(uint4*)(base + 24576 + o0) = pb1;
            *(uint4*)(base + 16384 + o1) = pb2;
            *(uint4*)(base + 24576 + o1) = pb3;
        }
        __syncthreads();
    }

#pragma unroll
    for (int mi = 0; mi < 4; ++mi)
#pragma unroll
        for (int j = 0; j < 4; ++j) {
            const int row = m0 + wm * 64 + mi * 16 + (lane >> 2);
            const int colL = wn * 32 + j * 8 + (lane & 3) * 2;
            const float b0v = sBias[colL], b1v = sBias[colL + 1];
            float x0 = acc[mi][j][0] + b0v, x1 = acc[mi][j][1] + b1v;
            float x2 = acc[mi][j][2] + b0v, x3 = acc[mi][j][3] + b1v;
            if (RELU) {
                x0 = fmaxf(x0, 0.f); x1 = fmaxf(x1, 0.f);
                x2 = fmaxf(x2, 0.f); x3 = fmaxf(x3, 0.f);
            }
            if (OUTBF) {
                uint32_t ph, pl;
                pack2(x0, x1, ph, pl);
                *(uint32_t*)(Chi + (size_t)row * ldo + n0 + colL) = ph;
                *(uint32_t*)(Clo + (size_t)row * ldo + n0 + colL) = pl;
                pack2(x2, x3, ph, pl);
                *(uint32_t*)(Chi + (size_t)(row + 8) * ldo + n0 + colL) = ph;
                *(uint32_t*)(Clo + (size_t)(row + 8) * ldo + n0 + colL) = pl;
            } else {
                *(float2*)(Cf + (size_t)row * ldo + n0 + colL) = make_float2(x0, x1);
                *(float2*)(Cf + (size_t)(row + 8) * ldo + n0 + colL) = make_float2(x2, x3);
            }
        }
}

// ------------------------- deltas (WIN=2, edge replicate) -------------------------
__global__ void deltas_k() {
    int idx = blockIdx.x * 256 + threadIdx.x;
    if (idx >= 32 * 1024 * 64) return;
    int c4 = idx & 63, t = (idx >> 6) & 1023, b = idx >> 16;
    const float4* h4 = (const float4*)d_h;
    size_t base = (size_t)b * 65536;
    int tp1 = min(t + 1, 1023), tm1 = max(t - 1, 0);
    int tp2 = min(t + 2, 1023), tm2 = max(t - 2, 0);
    float4 a = h4[base + (size_t)tp1 * 64 + c4];
    float4 bb = h4[base + (size_t)tm1 * 64 + c4];
    float4 c = h4[base + (size_t)tp2 * 64 + c4];
    float4 d = h4[base + (size_t)tm2 * 64 + c4];
    float4 z;
    z.x = (a.x - bb.x) * 0.5f + (c.x - d.x) * 0.25f;
    z.y = (a.y - bb.y) * 0.5f + (c.y - d.y) * 0.25f;
    z.z = (a.z - bb.z) * 0.5f + (c.z - d.z) * 0.25f;
    z.w = (a.w - bb.w) * 0.5f + (c.w - d.w) * 0.25f;
    ((float4*)d_d1)[base + (size_t)t * 64 + c4] = z;
}

// ------------------------- feat assembly (sorted) -> bf16 hi/lo -------------------------
__global__ void feat_k() {
    int idx = blockIdx.x * 256 + threadIdx.x;
    if (idx >= 32 * 1024 * 64) return;
    int c4 = idx & 63, t = (idx >> 6) & 1023, sb = idx >> 16;
    int b = d_order[sb];
    const float4* h4 = (const float4*)d_h;
    const float4* d14 = (const float4*)d_d1;
    size_t base = (size_t)b * 65536;
    size_t srow = base + (size_t)t * 64 + c4;
    float4 hv = h4[srow];
    float4 d1v = d14[srow];
    int tp1 = min(t + 1, 1023), tm1 = max(t - 1, 0);
    int tp2 = min(t + 2, 1023), tm2 = max(t - 2, 0);
    float4 a = d14[base + (size_t)tp1 * 64 + c4];
    float4 bb = d14[base + (size_t)tm1 * 64 + c4];
    float4 c = d14[base + (size_t)tp2 * 64 + c4];
    float4 d = d14[base + (size_t)tm2 * 64 + c4];
    float4 d2v;
    d2v.x = (a.x - bb.x) * 0.5f + (c.x - d.x) * 0.25f;
    d2v.y = (a.y - bb.y) * 0.5f + (c.y - d.y) * 0.25f;
    d2v.z = (a.z - bb.z) * 0.5f + (c.z - d.z) * 0.25f;
    d2v.w = (a.w - bb.w) * 0.5f + (c.w - d.w) * 0.25f;
    uint32_t* Fh32 = (uint32_t*)d_Fh;
    uint32_t* Fl32 = (uint32_t*)d_Fl;
    size_t ob = ((size_t)sb * 1024 + t) * 384;
    uint2 hp, lp;
    pack2(hv.x, hv.y, hp.x, lp.x);
    pack2(hv.z, hv.w, hp.y, lp.y);
    *(uint2*)&Fh32[ob + c4 * 2] = hp;
    *(uint2*)&Fl32[ob + c4 * 2] = lp;
    pack2(d1v.x, d1v.y, hp.x, lp.x);
    pack2(d1v.z, d1v.w, hp.y, lp.y);
    *(uint2*)&Fh32[ob + 128 + c4 * 2] = hp;
    *(uint2*)&Fl32[ob + 128 + c4 * 2] = lp;
    pack2(d2v.x, d2v.y, hp.x, lp.x);
    pack2(d2v.z, d2v.w, hp.y, lp.y);
    *(uint2*)&Fh32[ob + 256 + c4 * 2] = hp;
    *(uint2*)&Fl32[ob + 256 + c4 * 2] = lp;
}

// ------------------------- persistent bidirectional LSTM recurrence (HMMA) -------------------------
// 64 CTAs: dir = cta>>5, slice = cta&31 (8 h-units -> 32 gate rows). Per step:
// gate GEMM [32b x 32r x 256k] split-bf16 HMMA, K split across 8 warps, smem reduce.
// smem: AH 16K | AL 16K | BH 16K | BL 16K | P 8*32*33*4 -> 99328 B
__global__ void __launch_bounds__(256, 1) lstm_rec_k(
    const float* __restrict__ Whh_f, const float* __restrict__ Whh_b,
    const float* __restrict__ h0, const float* __restrict__ c0) {
    extern __shared__ char smc[];
    const int AHOF = 0, ALOF = 16384, BHOF = 32768, BLOF = 49152, POFF = 65536;
    float* P = (float*)(smc + POFF);
    const uint32_t sb = s2u(smc);
    const int tid = threadIdx.x, lane = tid & 31, wid = tid >> 5;
    const int dir = blockIdx.x >> 5, slice = blockIdx.x & 31;
    const float* Whh = dir ? Whh_b : Whh_f;

    // stage W slice (32 rows x 256 k) as bf16 hi/lo, ldmatrix layout
    for (int i = tid; i < 8192; i += 256) {
        int r = i >> 8, k = i & 255;
        int grow = ((r >> 3) << 8) + (slice << 3) + (r & 7);
        float w = __ldg(Whh + (size_t)grow * 256 + k);
        uint32_t pk = packhl(w);
        int c = k >> 3;
        int phys = (c & 24) | ((c ^ r) & 7);
        int off = r * 512 + phys * 16 + (k & 7) * 2;
        *(uint16_t*)(smc + BHOF + off) = (uint16_t)(pk >> 16);
        *(uint16_t*)(smc + BLOF + off) = (uint16_t)(pk & 0xffffu);
    }

    const int uq = tid >> 5, ub = tid & 31;     // unit j (0..7), batch
    const int kidx = (slice << 3) + uq;
    float creg = c0[(dir * 32 + ub) * 256 + kidx];
    d_Hc[0][dir][ub][kidx] = packhl(h0[(dir * 32 + ub) * 256 + kidx]);
    const int Lb = d_lens[ub];
    __syncthreads();
    if (tid == 0)
        asm volatile("red.release.gpu.global.add.u32 [%0], %1;"
                     :: "l"(&d_ctr2[dir]), "r"(1u) : "memory");

    const int rr = lane & 15, hs = lane >> 4;

    for (int t = 0; t < 1024; ++t) {
        // Z load first: latency overlaps the counter spin
        float zreg[4];
        {
            int tt = dir ? max(Lb - 1 - t, 0) : t;
            const float* zp = d_Z + ((size_t)ub * 1024 + tt) * 2048 + dir * 1024 + (slice << 3) + uq;
#pragma unroll
            for (int g = 0; g < 4; ++g) zreg[g] = __ldg(zp + (g << 8));
        }
        if (tid == 0) {
            unsigned tgt = 32u * (unsigned)(t + 1), v;
            do {
                asm volatile("ld.acquire.gpu.global.u32 %0, [%1];"
                             : "=r"(v) : "l"(&d_ctr2[dir]) : "memory");
            } while (v < tgt);
        }
        __syncthreads();
        // stage h(t): packed global -> smem bf16 hi/lo (ldmatrix layout)
        {
            const uint4* src = (const uint4*)&d_Hc[t & 1][dir][0][0];
#pragma unroll
            for (int q = 0; q < 4; ++q) {
                int p = q * 256 + tid;
                int b = p >> 5, c = p & 31;
                uint4 v0 = __ldcg(src + p * 2);
                uint4 v1 = __ldcg(src + p * 2 + 1);
                uint4 hiu, lou;
                hiu.x = __byte_perm(v0.x, v0.y, 0x7632);
                hiu.y = __byte_perm(v0.z, v0.w, 0x7632);
                hiu.z = __byte_perm(v1.x, v1.y, 0x7632);
                hiu.w = __byte_perm(v1.z, v1.w, 0x7632);
                lou.x = __byte_perm(v0.x, v0.y, 0x5410);
                lou.y = __byte_perm(v0.z, v0.w, 0x5410);
                lou.z = __byte_perm(v1.x, v1.y, 0x5410);
                lou.w = __byte_perm(v1.z, v1.w, 0x5410);
                int phys = (c & 24) | ((c ^ b) & 7);
                int off = b * 512 + phys * 16;
                *(uint4*)(smc + AHOF + off) = hiu;
                *(uint4*)(smc + ALOF + off) = lou;
            }
        }
        __syncthreads();
        // mma: warp wid owns k chunk wid*32
        float acc[2][4][4];
#pragma unroll
        for (int a = 0; a < 2; a++)
#pragma unroll
            for (int bq = 0; bq < 4; bq++)
#pragma unroll
                for (int q2 = 0; q2 < 4; q2++) acc[a][bq][q2] = 0.f;
        uint32_t ahr[2][2][4], alr[2][2][4], bhr[2][2][4], blr[2][2][4];
#pragma unroll
        for (int kt = 0; kt < 2; ++kt) {
            int cu = wid * 4 + kt * 2 + hs;
#pragma unroll
            for (int mt = 0; mt < 2; ++mt) {
                int row = mt * 16 + rr;
                int phys = (cu & 24) | ((cu ^ row) & 7);
                uint32_t off = (uint32_t)(row * 512 + phys * 16);
                ldsm4(ahr[mt][kt], sb + AHOF + off);
                ldsm4(alr[mt][kt], sb + ALOF + off);
            }
#pragma unroll
            for (int bt = 0; bt < 2; ++bt) {
                int row = bt * 16 + rr;
                int phys = (cu & 24) | ((cu ^ row) & 7);
                uint32_t off = (uint32_t)(row * 512 + phys * 16);
                ldsm4(bhr[bt][kt], sb + BHOF + off);
                ldsm4(blr[bt][kt], sb + BLOF + off);
            }
        }
#pragma unroll
        for (int mt = 0; mt < 2; ++mt)
#pragma unroll
            for (int bt = 0; bt < 2; ++bt)
#pragma unroll
                for (int nt = 0; nt < 2; ++nt)
#pragma unroll
                    for (int kt = 0; kt < 2; ++kt) {
                        float* ac = acc[mt][bt * 2 + nt];
                        mma16816(ac, ahr[mt][kt], bhr[bt][kt][nt], bhr[bt][kt][nt + 2]);
                        mma16816(ac, alr[mt][kt], bhr[bt][kt][nt], bhr[bt][kt][nt + 2]);
                        mma16816(ac, ahr[mt][kt], blr[bt][kt][nt], blr[bt][kt][nt + 2]);
                    }
#pragma unroll
        for (int mt = 0; mt < 2; ++mt)
#pragma unroll
            for (int bq = 0; bq < 4; ++bq) {
                int b = mt * 16 + (lane >> 2);
                int r = bq * 8 + (lane & 3) * 2;
                P[(wid * 32 + b) * 33 + r] = acc[mt][bq][0];
                P[(wid * 32 + b) * 33 + r + 1] = acc[mt][bq][1];
                P[(wid * 32 + b + 8) * 33 + r] = acc[mt][bq][2];
                P[(wid * 32 + b + 8) * 33 + r + 1] = acc[mt][bq][3];
            }
        __syncthreads();
        {
            float g4[4];
#pragma unroll
            for (int g = 0; g < 4; ++g) {
                float s = zreg[g];
                int ri = (g << 3) + uq;
#pragma unroll
                for (int w8 = 0; w8 < 8; ++w8) s += P[(w8 * 32 + ub) * 33 + ri];
                g4[g] = s;
            }
            float is = 1.f / (1.f + expf(-g4[0]));
            float fs = 1.f / (1.f + expf(-g4[1]));
            float gt = tanhf(g4[2]);
            float os = 1.f / (1.f + expf(-g4[3]));
            creg = fs * creg + is * gt;
            float hv = os * tanhf(creg);
            d_Hout[dir][t][kidx][ub] = hv;
            d_Hc[(t + 1) & 1][dir][ub][kidx] = packhl(hv);
        }
        __syncthreads();
        if (tid == 0)
            asm volatile("red.release.gpu.global.add.u32 [%0], %1;"
                         :: "l"(&d_ctr2[dir]), "r"(1u) : "memory");
    }
}

// ------------------------- output assembly -------------------------
__global__ void outk(float* __restrict__ out, int out_size) {
    int idx = blockIdx.x * 256 + threadIdx.x;
    if (idx >= out_size) return;
    if (idx < 16777216) {
        int j = idx & 511;
        int t = (idx >> 9) & 1023;
        int sb = idx >> 19;
        int L = d_lens[sb];
        float v = 0.f;
        if (t < L) {
            if (j < 256) v = d_Hout[0][t][j][sb];
            else v = d_Hout[1][L - 1 - t][j - 256][sb];
        }
        out[idx] = v;
    } else {
        int k = idx - 16777216;
        if (k < 32) out[idx] = (float)d_order[k];
        else out[idx] = 0.f;
    }
}

// ------------------------- launch -------------------------
extern "C" void kernel_launch(void* const* d_in, const int* in_sizes, int n_in,
                              void* d_out, int out_size) {
    const float* x = (const float*)d_in[0];
    const int* xlen = (const int*)d_in[1];
    const float* W0 = (const float*)d_in[2];
    const float* b0 = (const float*)d_in[3];
    const float* W1 = (const float*)d_in[4];
    const float* b1 = (const float*)d_in[5];
    const float* W2 = (const float*)d_in[6];
    const float* b2 = (const float*)d_in[7];
    const float* Wih_f = (const float*)d_in[8];
    const float* Whh_f = (const float*)d_in[9];
    const float* bih_f = (const float*)d_in[10];
    const float* bhh_f = (const float*)d_in[11];
    const float* Wih_b = (const float*)d_in[12];
    const float* Whh_b = (const float*)d_in[13];
    const float* bih_b = (const float*)d_in[14];
    const float* bhh_b = (const float*)d_in[15];
    const float* h0 = (const float*)d_in[16];
    const float* c0 = (const float*)d_in[17];
    float* out = (float*)d_out;

    void *p_h, *p_Z, *p_bias;
    void *p_wch, *p_wcl, *p_w1h, *p_w1l, *p_w2h, *p_w2l;
    void *p_a0h, *p_a0l, *p_a1h, *p_a1l, *p_fh, *p_fl;
    cudaGetSymbolAddress(&p_h, d_h);
    cudaGetSymbolAddress(&p_Z, d_Z);
    cudaGetSymbolAddress(&p_bias, d_biascat);
    cudaGetSymbolAddress(&p_wch, d_Wch);
    cudaGetSymbolAddress(&p_wcl, d_Wcl);
    cudaGetSymbolAddress(&p_w1h, d_W1h);
    cudaGetSymbolAddress(&p_w1l, d_W1l);
    cudaGetSymbolAddress(&p_w2h, d_W2h);
    cudaGetSymbolAddress(&p_w2l, d_W2l);
    cudaGetSymbolAddress(&p_a0h, d_A0h);
    cudaGetSymbolAddress(&p_a0l, d_A0l);
    cudaGetSymbolAddress(&p_a1h, d_A1h);
    cudaGetSymbolAddress(&p_a1l, d_A1l);
    cudaGetSymbolAddress(&p_fh, d_Fh);
    cudaGetSymbolAddress(&p_fl, d_Fl);

    cudaFuncSetAttribute(gemm_mma_k<0, 0>, cudaFuncAttributeMaxDynamicSharedMemorySize, 66048);
    cudaFuncSetAttribute(gemm_mma_k<1, 0>, cudaFuncAttributeMaxDynamicSharedMemorySize, 66048);
    cudaFuncSetAttribute(gemm_mma_k<1, 1>, cudaFuncAttributeMaxDynamicSharedMemorySize, 66048);
    cudaFuncSetAttribute(lstm_rec_k, cudaFuncAttributeMaxDynamicSharedMemorySize, 99328);

    compute_order_k<<<1, 32>>>(xlen);
    bias_k<<<2, 1024>>>(bih_f, bhh_f, bih_b, bhh_b);

    // pre-convert static weights to bf16 hi/lo
    convw_k<<<(131072 + 255) / 256, 256>>>(W1, (uint16_t*)p_w1h, (uint16_t*)p_w1l, 131072);
    convw_k<<<(65536 + 255) / 256, 256>>>(W2, (uint16_t*)p_w2h, (uint16_t*)p_w2l, 65536);
    convw_k<<<(393216 + 255) / 256, 256>>>(Wih_f, (uint16_t*)p_wch, (uint16_t*)p_wcl, 393216);
    convw_k<<<(393216 + 255) / 256, 256>>>(
        Wih_b, (uint16_t*)p_wch + 1024 * 768, (uint16_t*)p_wcl + 1024 * 768, 393216);

    // encoder (activations flow as bf16 hi/lo)
    gemm_relu_k<<<dim3(4, 256), 256>>>(x, W0, b0, (uint16_t*)p_a0h, (uint16_t*)p_a0l,
                                       32768, 512, 80);
    gemm_mma_k<1, 1><<<dim3(4, 256), 256, 66048>>>(
        (const uint16_t*)p_a0h, (const uint16_t*)p_a0l,
        (const uint16_t*)p_w1h, (const uint16_t*)p_w1l,
        b1, nullptr, (uint16_t*)p_a1h, (uint16_t*)p_a1l, 512, 512);
    gemm_mma_k<1, 0><<<dim3(2, 256), 256, 66048>>>(
        (const uint16_t*)p_a1h, (const uint16_t*)p_a1l,
        (const uint16_t*)p_w2h, (const uint16_t*)p_w2l,
        b2, (float*)p_h, nullptr, nullptr, 512, 256);

    deltas_k<<<8192, 256>>>();
    feat_k<<<8192, 256>>>();

    // Z = feat @ [Wih_f ; Wih_b]^T + biascat
    gemm_mma_k<0, 0><<<dim3(16, 256), 256, 66048>>>(
        (const uint16_t*)p_fh, (const uint16_t*)p_fl,
        (const uint16_t*)p_wch, (const uint16_t*)p_wcl,
        (const float*)p_bias, (float*)p_Z, nullptr, nullptr, 768, 2048);

    lstm_rec_k<<<64, 256, 99328>>>(Whh_f, Whh_b, h0, c0);

    outk<<<(out_size + 255) / 256, 256>>>(out, out_size);
}

// round 8
// speedup vs baseline: 1.4156x; 1.1434x over previous
#include <cuda_runtime.h>
#include <math.h>
#include <stdint.h>
#include <string.h>

// B=32, T=1024, D_IN=80, enc: 80->512->512->256 (ReLU), F=768, 4H=1024, H=256

// ------------------------- device scratch -------------------------
__device__ float d_h[32768 * 256];
__device__ float d_Z[32768 * 2048];        // [b][t][2048]: cols 0..1023 fwd, 1024..2047 bwd
__device__ float d_biascat[2048];
__device__ uint32_t d_Hc[2][2][32][256];   // [parity][dir][b][k] packed (bf16hi<<16)|bf16lo
__device__ float d_Hout[2][1024][256][32]; // [dir][t][k][b]
__device__ int d_order[32];
__device__ int d_lens[32];
__device__ unsigned d_ctr2[2];
// pre-converted bf16 hi/lo weights + activations
__device__ uint16_t d_Wch[2048 * 768], d_Wcl[2048 * 768];
__device__ uint16_t d_W1h[512 * 512], d_W1l[512 * 512];
__device__ uint16_t d_W2h[256 * 512], d_W2l[256 * 512];
__device__ uint16_t d_A0h[32768 * 512], d_A0l[32768 * 512];
__device__ uint16_t d_A1h[32768 * 512], d_A1l[32768 * 512];
__device__ uint16_t d_Fh[32768 * 768], d_Fl[32768 * 768];

// ------------------------- helpers -------------------------
__device__ __forceinline__ uint32_t s2u(const void* p) {
    uint32_t a;
    asm("{ .reg .u64 t; cvta.to.shared.u64 t, %1; cvt.u32.u64 %0, t; }" : "=r"(a) : "l"(p));
    return a;
}
__device__ __forceinline__ uint32_t cvt2bf(float lo, float hi) {
    uint32_t r;
    asm("cvt.rn.satfinite.bf16x2.f32 %0, %1, %2;" : "=r"(r) : "f"(hi), "f"(lo));
    return r;
}
__device__ __forceinline__ uint32_t packhl(float v) {
    uint32_t u = cvt2bf(0.f, v);
    float resid = v - __uint_as_float(u & 0xffff0000u);
    return cvt2bf(resid, v);
}
__device__ __forceinline__ void pack2(float x0, float x1, uint32_t& ph, uint32_t& pl) {
    ph = cvt2bf(x0, x1);
    float r0 = x0 - __uint_as_float(ph << 16);
    float r1 = x1 - __uint_as_float(ph & 0xffff0000u);
    pl = cvt2bf(r0, r1);
}
__device__ __forceinline__ void ldsm4(uint32_t* r, uint32_t addr) {
    asm volatile("ldmatrix.sync.aligned.m8n8.x4.shared.b16 {%0,%1,%2,%3}, [%4];"
                 : "=r"(r[0]), "=r"(r[1]), "=r"(r[2]), "=r"(r[3]) : "r"(addr));
}
__device__ __forceinline__ void mma16816(float* c, const uint32_t* a, uint32_t b0, uint32_t b1) {
    asm volatile(
        "mma.sync.aligned.m16n8k16.row.col.f32.bf16.bf16.f32 "
        "{%0,%1,%2,%3}, {%4,%5,%6,%7}, {%8,%9}, {%0,%1,%2,%3};"
        : "+f"(c[0]), "+f"(c[1]), "+f"(c[2]), "+f"(c[3])
        : "r"(a[0]), "r"(a[1]), "r"(a[2]), "r"(a[3]), "r"(b0), "r"(b1));
}
#define SWZB(row, c) ((((uint32_t)(row)) << 6) + ((((uint32_t)(c) ^ (((uint32_t)(row) >> 1) & 3))) << 4))

__device__ __forceinline__ void conv_range(const float* __restrict__ src,
                                           uint16_t* __restrict__ dh, uint16_t* __restrict__ dl,
                                           int npairs, int tid, int nth) {
    for (int i = tid; i < npairs; i += nth) {
        float2 v = ((const float2*)src)[i];
        uint32_t ph, pl;
        pack2(v.x, v.y, ph, pl);
        ((uint32_t*)dh)[i] = ph;
        ((uint32_t*)dl)[i] = pl;
    }
}

// ------------------------- fp32 GEMM (K=80 layer 0) + fused prep blocks -------------------------
__global__ void __launch_bounds__(256) gemm_relu_k(
    const float* __restrict__ A, const float* __restrict__ W,
    const float* __restrict__ bias, uint16_t* __restrict__ Chi, uint16_t* __restrict__ Clo,
    int M, int N, int K,
    const int* __restrict__ xlen,
    const float* __restrict__ W1, const float* __restrict__ W2,
    const float* __restrict__ Wihf, const float* __restrict__ Wihb,
    const float* __restrict__ bihf, const float* __restrict__ bhhf,
    const float* __restrict__ bihb, const float* __restrict__ bhhb) {
    if (blockIdx.y >= 256) {
        // prep blocks: order/lens/ctr, biascat, weight conversion
        const int pid = (blockIdx.y - 256) * gridDim.x + blockIdx.x;
        const int nth = (gridDim.y - 256) * gridDim.x * 256;
        const int ptid = pid * 256 + threadIdx.x;
        if (ptid == 0) {
            unsigned used = 0;
            for (int p = 0; p < 32; ++p) {
                int best = -1, bl = -2147483647;
                for (int j = 0; j < 32; ++j) {
                    if (used & (1u << j)) continue;
                    int L = xlen[j];
                    if (L > bl) { bl = L; best = j; }
                }
                used |= (1u << best);
                d_order[p] = best;
                d_lens[p] = bl;
            }
            d_ctr2[0] = 0u;
            d_ctr2[1] = 0u;
        }
        if (ptid < 1024) d_biascat[ptid] = bihf[ptid] + bhhf[ptid];
        else if (ptid < 2048) d_biascat[ptid] = bihb[ptid - 1024] + bhhb[ptid - 1024];
        conv_range(W1, d_W1h, d_W1l, 131072, ptid, nth);
        conv_range(W2, d_W2h, d_W2l, 65536, ptid, nth);
        conv_range(Wihf, d_Wch, d_Wcl, 393216, ptid, nth);
        conv_range(Wihb, d_Wch + 1024 * 768, d_Wcl + 1024 * 768, 393216, ptid, nth);
        return;
    }
    __shared__ float As[8][132];
    __shared__ float Ws[8][132];
    const int tid = threadIdx.x;
    const int n0 = blockIdx.x * 128, m0 = blockIdx.y * 128;
    const int lm = tid >> 1, lq = (tid & 1) * 4;
    const float* arow = A + (size_t)(m0 + lm) * K + lq;
    const float* wrow = W + (size_t)(n0 + lm) * K + lq;
    const int tx = tid & 15, ty = tid >> 4;
    float acc[8][8];
#pragma unroll
    for (int i = 0; i < 8; i++)
#pragma unroll
        for (int j = 0; j < 8; j++) acc[i][j] = 0.f;

    for (int k0 = 0; k0 < K; k0 += 8) {
        float4 av = *(const float4*)(arow + k0);
        float4 wv = *(const float4*)(wrow + k0);
        __syncthreads();
        As[lq + 0][lm] = av.x; As[lq + 1][lm] = av.y;
        As[lq + 2][lm] = av.z; As[lq + 3][lm] = av.w;
        Ws[lq + 0][lm] = wv.x; Ws[lq + 1][lm] = wv.y;
        Ws[lq + 2][lm] = wv.z; Ws[lq + 3][lm] = wv.w;
        __syncthreads();
#pragma unroll
        for (int k = 0; k < 8; k++) {
            float a[8], b[8];
            *(float4*)(a) = *(const float4*)&As[k][ty * 8];
            *(float4*)(a + 4) = *(const float4*)&As[k][ty * 8 + 4];
            *(float4*)(b) = *(const float4*)&Ws[k][tx * 8];
            *(float4*)(b + 4) = *(const float4*)&Ws[k][tx * 8 + 4];
#pragma unroll
            for (int i = 0; i < 8; i++)
#pragma unroll
                for (int j = 0; j < 8; j++) acc[i][j] += a[i] * b[j];
        }
    }
    float bs[8];
    *(float4*)bs = *(const float4*)&bias[n0 + tx * 8];
    *(float4*)(bs + 4) = *(const float4*)&bias[n0 + tx * 8 + 4];
#pragma unroll
    for (int i = 0; i < 8; i++) {
        size_t base = (size_t)(m0 + ty * 8 + i) * N + n0 + tx * 8;
        float v[8];
#pragma unroll
        for (int j = 0; j < 8; j++) v[j] = fmaxf(acc[i][j] + bs[j], 0.f);
        uint4 hv, lv;
        pack2(v[0], v[1], hv.x, lv.x);
        pack2(v[2], v[3], hv.y, lv.y);
        pack2(v[4], v[5], hv.z, lv.z);
        pack2(v[6], v[7], hv.w, lv.w);
        *(uint4*)(Chi + base) = hv;
        *(uint4*)(Clo + base) = lv;
    }
}

// ------------------------- HMMA split-bf16 GEMM (all operands pre-converted) -------------------------
template <int RELU, int OUTBF>
__global__ void __launch_bounds__(256) gemm_mma_k(
    const uint16_t* __restrict__ Ahi, const uint16_t* __restrict__ Alo,
    const uint16_t* __restrict__ Bhi, const uint16_t* __restrict__ Blo,
    const float* __restrict__ bias, float* __restrict__ Cf,
    uint16_t* __restrict__ Chi, uint16_t* __restrict__ Clo,
    int K, int ldo) {
    extern __shared__ char smc[];
    const int tid = threadIdx.x, lane = tid & 31, wid = tid >> 5;
    const int wm = wid >> 2, wn = wid & 3;
    const int n0 = blockIdx.x * 128, m0 = blockIdx.y * 128;
    const int NCH = K >> 5;
    const uint32_t sbase = s2u(smc);
    float* sBias = (float*)(smc + 65536);
    if (tid < 128) sBias[tid] = bias[n0 + tid];

    const int ra = tid >> 2, ca = tid & 3;
    const int ldu = K >> 3;
    const uint4* Ah0 = (const uint4*)Ahi + (size_t)(m0 + ra) * ldu + ca;
    const uint4* Al0 = (const uint4*)Alo + (size_t)(m0 + ra) * ldu + ca;
    const uint4* Ah1 = (const uint4*)Ahi + (size_t)(m0 + 64 + ra) * ldu + ca;
    const uint4* Al1 = (const uint4*)Alo + (size_t)(m0 + 64 + ra) * ldu + ca;
    const uint4* Bh0 = (const uint4*)Bhi + (size_t)(n0 + ra) * ldu + ca;
    const uint4* Bl0 = (const uint4*)Blo + (size_t)(n0 + ra) * ldu + ca;
    const uint4* Bh1 = (const uint4*)Bhi + (size_t)(n0 + 64 + ra) * ldu + ca;
    const uint4* Bl1 = (const uint4*)Blo + (size_t)(n0 + 64 + ra) * ldu + ca;

    float acc[4][4][4];
#pragma unroll
    for (int mi = 0; mi < 4; mi++)
#pragma unroll
        for (int j = 0; j < 4; j++)
#pragma unroll
            for (int q = 0; q < 4; q++) acc[mi][j][q] = 0.f;

    const uint32_t o0 = SWZB(ra, ca), o1 = SWZB(64 + ra, ca);
    {
        char* base = smc;
        *(uint4*)(base + o0) = *Ah0;
        *(uint4*)(base + 8192 + o0) = *Al0;
        *(uint4*)(base + o1) = *Ah1;
        *(uint4*)(base + 8192 + o1) = *Al1;
        *(uint4*)(base + 16384 + o0) = *Bh0;
        *(uint4*)(base + 24576 + o0) = *Bl0;
        *(uint4*)(base + 16384 + o1) = *Bh1;
        *(uint4*)(base + 24576 + o1) = *Bl1;
    }
    __syncthreads();

    for (int i = 0; i < NCH; ++i) {
        uint4 pa0, pa1, pa2, pa3, pb0, pb1, pb2, pb3;
        const bool more = (i + 1 < NCH);
        if (more) {
            const int ku = (i + 1) << 2;
            pa0 = Ah0[ku]; pa1 = Al0[ku]; pa2 = Ah1[ku]; pa3 = Al1[ku];
            pb0 = Bh0[ku]; pb1 = Bl0[ku]; pb2 = Bh1[ku]; pb3 = Bl1[ku];
        }
        const uint32_t ab = sbase + (i & 1) * 32768;
        const uint32_t bb = ab + 16384;
#pragma unroll
        for (int ks = 0; ks < 2; ++ks) {
            const int r = lane & 15;
            const int cu = (ks << 1) + (lane >> 4);
            uint32_t ah[4][4], al[4][4], bh[2][4], bl[2][4];
#pragma unroll
            for (int mi = 0; mi < 4; ++mi) {
                uint32_t off = SWZB(wm * 64 + mi * 16 + r, cu);
                ldsm4(ah[mi], ab + off);
                ldsm4(al[mi], ab + 8192 + off);
            }
#pragma unroll
            for (int ni = 0; ni < 2; ++ni) {
                uint32_t off = SWZB(wn * 32 + ni * 16 + r, cu);
                ldsm4(bh[ni], bb + off);
                ldsm4(bl[ni], bb + 8192 + off);
            }
#pragma unroll
            for (int mi = 0; mi < 4; ++mi)
#pragma unroll
                for (int j = 0; j < 4; ++j) {
                    const int ni = j >> 1, s = j & 1;
                    mma16816(acc[mi][j], ah[mi], bh[ni][s], bh[ni][s + 2]);
                    mma16816(acc[mi][j], al[mi], bh[ni][s], bh[ni][s + 2]);
                    mma16816(acc[mi][j], ah[mi], bl[ni][s], bl[ni][s + 2]);
                }
        }
        if (more) {
            char* base = smc + ((i + 1) & 1) * 32768;
            *(uint4*)(base + o0) = pa0;
            *(uint4*)(base + 8192 + o0) = pa1;
            *(uint4*)(base + o1) = pa2;
            *(uint4*)(base + 8192 + o1) = pa3;
            *(uint4*)(base + 16384 + o0) = pb0;
            *(uint4*)(base + 24576 + o0) = pb1;
            *(uint4*)(base + 16384 + o1) = pb2;
            *(uint4*)(base + 24576 + o1) = pb3;
        }
        __syncthreads();
    }

#pragma unroll
    for (int mi = 0; mi < 4; ++mi)
#pragma unroll
        for (int j = 0; j < 4; ++j) {
            const int row = m0 + wm * 64 + mi * 16 + (lane >> 2);
            const int colL = wn * 32 + j * 8 + (lane & 3) * 2;
            const float b0v = sBias[colL], b1v = sBias[colL + 1];
            float x0 = acc[mi][j][0] + b0v, x1 = acc[mi][j][1] + b1v;
            float x2 = acc[mi][j][2] + b0v, x3 = acc[mi][j][3] + b1v;
            if (RELU) {
                x0 = fmaxf(x0, 0.f); x1 = fmaxf(x1, 0.f);
                x2 = fmaxf(x2, 0.f); x3 = fmaxf(x3, 0.f);
            }
            if (OUTBF) {
                uint32_t ph, pl;
                pack2(x0, x1, ph, pl);
                *(uint32_t*)(Chi + (size_t)row * ldo + n0 + colL) = ph;
                *(uint32_t*)(Clo + (size_t)row * ldo + n0 + colL) = pl;
                pack2(x2, x3, ph, pl);
                *(uint32_t*)(Chi + (size_t)(row + 8) * ldo + n0 + colL) = ph;
                *(uint32_t*)(Clo + (size_t)(row + 8) * ldo + n0 + colL) = pl;
            } else {
                *(float2*)(Cf + (size_t)row * ldo + n0 + colL) = make_float2(x0, x1);
                *(float2*)(Cf + (size_t)(row + 8) * ldo + n0 + colL) = make_float2(x2, x3);
            }
        }
}

// ------------------------- fused deltas(2x) + feat assembly -> bf16 hi/lo -------------------------
__device__ __forceinline__ float4 d1_at(const float4* __restrict__ h4, size_t base, int t, int c4) {
    int tp1 = min(t + 1, 1023), tm1 = max(t - 1, 0);
    int tp2 = min(t + 2, 1023), tm2 = max(t - 2, 0);
    float4 a = h4[base + (size_t)tp1 * 64 + c4];
    float4 b = h4[base + (size_t)tm1 * 64 + c4];
    float4 c = h4[base + (size_t)tp2 * 64 + c4];
    float4 d = h4[base + (size_t)tm2 * 64 + c4];
    float4 z;
    z.x = (a.x - b.x) * 0.5f + (c.x - d.x) * 0.25f;
    z.y = (a.y - b.y) * 0.5f + (c.y - d.y) * 0.25f;
    z.z = (a.z - b.z) * 0.5f + (c.z - d.z) * 0.25f;
    z.w = (a.w - b.w) * 0.5f + (c.w - d.w) * 0.25f;
    return z;
}

__global__ void feat_k() {
    int idx = blockIdx.x * 256 + threadIdx.x;
    if (idx >= 32 * 1024 * 64) return;
    int c4 = idx & 63, t = (idx >> 6) & 1023, sb = idx >> 16;
    int b = d_order[sb];
    const float4* h4 = (const float4*)d_h;
    size_t base = (size_t)b * 65536;
    float4 hv = h4[base + (size_t)t * 64 + c4];
    float4 d1v = d1_at(h4, base, t, c4);
    int tp1 = min(t + 1, 1023), tm1 = max(t - 1, 0);
    int tp2 = min(t + 2, 1023), tm2 = max(t - 2, 0);
    float4 a = d1_at(h4, base, tp1, c4);
    float4 bb = d1_at(h4, base, tm1, c4);
    float4 c = d1_at(h4, base, tp2, c4);
    float4 d = d1_at(h4, base, tm2, c4);
    float4 d2v;
    d2v.x = (a.x - bb.x) * 0.5f + (c.x - d.x) * 0.25f;
    d2v.y = (a.y - bb.y) * 0.5f + (c.y - d.y) * 0.25f;
    d2v.z = (a.z - bb.z) * 0.5f + (c.z - d.z) * 0.25f;
    d2v.w = (a.w - bb.w) * 0.5f + (c.w - d.w) * 0.25f;
    uint32_t* Fh32 = (uint32_t*)d_Fh;
    uint32_t* Fl32 = (uint32_t*)d_Fl;
    size_t ob = ((size_t)sb * 1024 + t) * 384;
    uint2 hp, lp;
    pack2(hv.x, hv.y, hp.x, lp.x);
    pack2(hv.z, hv.w, hp.y, lp.y);
    *(uint2*)&Fh32[ob + c4 * 2] = hp;
    *(uint2*)&Fl32[ob + c4 * 2] = lp;
    pack2(d1v.x, d1v.y, hp.x, lp.x);
    pack2(d1v.z, d1v.w, hp.y, lp.y);
    *(uint2*)&Fh32[ob + 128 + c4 * 2] = hp;
    *(uint2*)&Fl32[ob + 128 + c4 * 2] = lp;
    pack2(d2v.x, d2v.y, hp.x, lp.x);
    pack2(d2v.z, d2v.w, hp.y, lp.y);
    *(uint2*)&Fh32[ob + 256 + c4 * 2] = hp;
    *(uint2*)&Fl32[ob + 256 + c4 * 2] = lp;
}

// ------------------------- persistent bidirectional LSTM recurrence (HMMA) -------------------------
// 128 CTAs: dir = cta>>6, slice = cta&63 (4 h-units -> 16 gate rows). Per step:
// gate GEMM [32b x 16r x 256k] split-bf16 HMMA, K split across 8 warps, smem reduce.
// smem: AH 16K | AL 16K | BH 8K | BL 8K | P 8*32*17*4 -> 66560 B
__global__ void __launch_bounds__(256, 1) lstm_rec_k(
    const float* __restrict__ Whh_f, const float* __restrict__ Whh_b,
    const float* __restrict__ h0, const float* __restrict__ c0) {
    extern __shared__ char smc[];
    const int AHOF = 0, ALOF = 16384, BHOF = 32768, BLOF = 40960, POFF = 49152;
    float* P = (float*)(smc + POFF);
    const uint32_t sb = s2u(smc);
    const int tid = threadIdx.x, lane = tid & 31, wid = tid >> 5;
    const int dir = blockIdx.x >> 6, slice = blockIdx.x & 63;
    const float* Whh = dir ? Whh_b : Whh_f;

    // stage W slice (16 rows x 256 k) as bf16 hi/lo, ldmatrix layout
    for (int i = tid; i < 4096; i += 256) {
        int r = i >> 8, k = i & 255;
        int grow = ((r >> 2) << 8) + (slice << 2) + (r & 3);
        float w = __ldg(Whh + (size_t)grow * 256 + k);
        uint32_t pk = packhl(w);
        int c = k >> 3;
        int phys = (c & 24) | ((c ^ r) & 7);
        int off = r * 512 + phys * 16 + (k & 7) * 2;
        *(uint16_t*)(smc + BHOF + off) = (uint16_t)(pk >> 16);
        *(uint16_t*)(smc + BLOF + off) = (uint16_t)(pk & 0xffffu);
    }

    const int uq = tid >> 5, ub = tid & 31;
    const int kidx = (slice << 2) + uq;
    float creg = 0.f;
    int Lb = 0;
    if (tid < 128) {
        creg = c0[(dir * 32 + ub) * 256 + kidx];
        d_Hc[0][dir][ub][kidx] = packhl(h0[(dir * 32 + ub) * 256 + kidx]);
        Lb = d_lens[ub];
    }
    __syncthreads();
    if (tid == 0)
        asm volatile("red.release.gpu.global.add.u32 [%0], %1;"
                     :: "l"(&d_ctr2[dir]), "r"(1u) : "memory");

    const int rr = lane & 15, hs = lane >> 4;

    for (int t = 0; t < 1024; ++t) {
        // Z load first: latency overlaps the counter spin
        float zreg[4];
        if (tid < 128) {
            int tt = dir ? max(Lb - 1 - t, 0) : t;
            const float* zp = d_Z + ((size_t)ub * 1024 + tt) * 2048 + dir * 1024 + (slice << 2) + uq;
#pragma unroll
            for (int g = 0; g < 4; ++g) zreg[g] = __ldg(zp + (g << 8));
        }
        if (tid == 0) {
            unsigned tgt = 64u * (unsigned)(t + 1), v;
            do {
                asm volatile("ld.acquire.gpu.global.u32 %0, [%1];"
                             : "=r"(v) : "l"(&d_ctr2[dir]) : "memory");
            } while (v < tgt);
        }
        __syncthreads();
        // stage h(t): packed global -> smem bf16 hi/lo (ldmatrix layout)
        {
            const uint4* src = (const uint4*)&d_Hc[t & 1][dir][0][0];
#pragma unroll
            for (int q = 0; q < 4; ++q) {
                int p = q * 256 + tid;
                int b = p >> 5, c = p & 31;
                uint4 v0 = __ldcg(src + p * 2);
                uint4 v1 = __ldcg(src + p * 2 + 1);
                uint4 hiu, lou;
                hiu.x = __byte_perm(v0.x, v0.y, 0x7632);
                hiu.y = __byte_perm(v0.z, v0.w, 0x7632);
                hiu.z = __byte_perm(v1.x, v1.y, 0x7632);
                hiu.w = __byte_perm(v1.z, v1.w, 0x7632);
                lou.x = __byte_perm(v0.x, v0.y, 0x5410);
                lou.y = __byte_perm(v0.z, v0.w, 0x5410);
                lou.z = __byte_perm(v1.x, v1.y, 0x5410);
                lou.w = __byte_perm(v1.z, v1.w, 0x5410);
                int phys = (c & 24) | ((c ^ b) & 7);
                int off = b * 512 + phys * 16;
                *(uint4*)(smc + AHOF + off) = hiu;
                *(uint4*)(smc + ALOF + off) = lou;
            }
        }
        __syncthreads();
        // mma: warp wid owns k chunk wid*32
        float acc[2][2][4];
#pragma unroll
        for (int a = 0; a < 2; a++)
#pragma unroll
            for (int bq = 0; bq < 2; bq++)
#pragma unroll
                for (int q2 = 0; q2 < 4; q2++) acc[a][bq][q2] = 0.f;
        uint32_t ahr[2][2][4], alr[2][2][4], bhr[2][4], blr[2][4];
#pragma unroll
        for (int kt = 0; kt < 2; ++kt) {
            int cu = wid * 4 + kt * 2 + hs;
#pragma unroll
            for (int mt = 0; mt < 2; ++mt) {
                int row = mt * 16 + rr;
                int phys = (cu & 24) | ((cu ^ row) & 7);
                uint32_t off = (uint32_t)(row * 512 + phys * 16);
                ldsm4(ahr[mt][kt], sb + AHOF + off);
                ldsm4(alr[mt][kt], sb + ALOF + off);
            }
            {
                int row = rr;
                int phys = (cu & 24) | ((cu ^ rr) & 7);
                uint32_t off = (uint32_t)(rr * 512 + phys * 16);
                ldsm4(bhr[kt], sb + BHOF + off);
                ldsm4(blr[kt], sb + BLOF + off);
            }
        }
#pragma unroll
        for (int mt = 0; mt < 2; ++mt)
#pragma unroll
            for (int nt = 0; nt < 2; ++nt)
#pragma unroll
                for (int kt = 0; kt < 2; ++kt) {
                    mma16816(acc[mt][nt], ahr[mt][kt], bhr[kt][nt], bhr[kt][nt + 2]);
                    mma16816(acc[mt][nt], alr[mt][kt], bhr[kt][nt], bhr[kt][nt + 2]);
                    mma16816(acc[mt][nt], ahr[mt][kt], blr[kt][nt], blr[kt][nt + 2]);
                }
#pragma unroll
        for (int mt = 0; mt < 2; ++mt)
#pragma unroll
            for (int nt = 0; nt < 2; ++nt) {
                int b = mt * 16 + (lane >> 2);
                int r = nt * 8 + (lane & 3) * 2;
                P[(wid * 32 + b) * 17 + r] = acc[mt][nt][0];
                P[(wid * 32 + b) * 17 + r + 1] = acc[mt][nt][1];
                P[(wid * 32 + b + 8) * 17 + r] = acc[mt][nt][2];
                P[(wid * 32 + b + 8) * 17 + r + 1] = acc[mt][nt][3];
            }
        __syncthreads();
        if (tid < 128) {
            float g4[4];
#pragma unroll
            for (int g = 0; g < 4; ++g) {
                float s = zreg[g];
                int ri = 4 * g + uq;
#pragma unroll
                for (int w8 = 0; w8 < 8; ++w8) s += P[(w8 * 32 + ub) * 17 + ri];
                g4[g] = s;
            }
            float is = 1.f / (1.f + expf(-g4[0]));
            float fs = 1.f / (1.f + expf(-g4[1]));
            float gt = tanhf(g4[2]);
            float os = 1.f / (1.f + expf(-g4[3]));
            creg = fs * creg + is * gt;
            float hv = os * tanhf(creg);
            d_Hout[dir][t][kidx][ub] = hv;
            d_Hc[(t + 1) & 1][dir][ub][kidx] = packhl(hv);
        }
        __syncthreads();
        if (tid == 0)
            asm volatile("red.release.gpu.global.add.u32 [%0], %1;"
                         :: "l"(&d_ctr2[dir]), "r"(1u) : "memory");
    }
}

// ------------------------- output assembly -------------------------
__global__ void outk(float* __restrict__ out, int out_size) {
    int idx = blockIdx.x * 256 + threadIdx.x;
    if (idx >= out_size) return;
    if (idx < 16777216) {
        int j = idx & 511;
        int t = (idx >> 9) & 1023;
        int sb = idx >> 19;
        int L = d_lens[sb];
        float v = 0.f;
        if (t < L) {
            if (j < 256) v = d_Hout[0][t][j][sb];
            else v = d_Hout[1][L - 1 - t][j - 256][sb];
        }
        out[idx] = v;
    } else {
        int k = idx - 16777216;
        if (k < 32) out[idx] = (float)d_order[k];
        else out[idx] = 0.f;
    }
}

// ------------------------- launch -------------------------
extern "C" void kernel_launch(void* const* d_in, const int* in_sizes, int n_in,
                              void* d_out, int out_size) {
    const float* x = (const float*)d_in[0];
    const int* xlen = (const int*)d_in[1];
    const float* W0 = (const float*)d_in[2];
    const float* b0 = (const float*)d_in[3];
    const float* W1 = (const float*)d_in[4];
    const float* b1 = (const float*)d_in[5];
    const float* W2 = (const float*)d_in[6];
    const float* b2 = (const float*)d_in[7];
    const float* Wih_f = (const float*)d_in[8];
    const float* Whh_f = (const float*)d_in[9];
    const float* bih_f = (const float*)d_in[10];
    const float* bhh_f = (const float*)d_in[11];
    const float* Wih_b = (const float*)d_in[12];
    const float* Whh_b = (const float*)d_in[13];
    const float* bih_b = (const float*)d_in[14];
    const float* bhh_b = (const float*)d_in[15];
    const float* h0 = (const float*)d_in[16];
    const float* c0 = (const float*)d_in[17];
    float* out = (float*)d_out;

    void *p_h, *p_Z, *p_bias;
    void *p_wch, *p_wcl, *p_w1h, *p_w1l, *p_w2h, *p_w2l;
    void *p_a0h, *p_a0l, *p_a1h, *p_a1l, *p_fh, *p_fl;
    cudaGetSymbolAddress(&p_h, d_h);
    cudaGetSymbolAddress(&p_Z, d_Z);
    cudaGetSymbolAddress(&p_bias, d_biascat);
    cudaGetSymbolAddress(&p_wch, d_Wch);
    cudaGetSymbolAddress(&p_wcl, d_Wcl);
    cudaGetSymbolAddress(&p_w1h, d_W1h);
    cudaGetSymbolAddress(&p_w1l, d_W1l);
    cudaGetSymbolAddress(&p_w2h, d_W2h);
    cudaGetSymbolAddress(&p_w2l, d_W2l);
    cudaGetSymbolAddress(&p_a0h, d_A0h);
    cudaGetSymbolAddress(&p_a0l, d_A0l);
    cudaGetSymbolAddress(&p_a1h, d_A1h);
    cudaGetSymbolAddress(&p_a1l, d_A1l);
    cudaGetSymbolAddress(&p_fh, d_Fh);
    cudaGetSymbolAddress(&p_fl, d_Fl);

    cudaFuncSetAttribute(gemm_mma_k<0, 0>, cudaFuncAttributeMaxDynamicSharedMemorySize, 66048);
    cudaFuncSetAttribute(gemm_mma_k<1, 0>, cudaFuncAttributeMaxDynamicSharedMemorySize, 66048);
    cudaFuncSetAttribute(gemm_mma_k<1, 1>, cudaFuncAttributeMaxDynamicSharedMemorySize, 66048);
    cudaFuncSetAttribute(lstm_rec_k, cudaFuncAttributeMaxDynamicSharedMemorySize, 66560);

    // launch 0: enc L0 GEMM + fused prep (order/bias/weight-convert in extra blocks)
    gemm_relu_k<<<dim3(4, 272), 256>>>(x, W0, b0, (uint16_t*)p_a0h, (uint16_t*)p_a0l,
                                       32768, 512, 80, xlen, W1, W2, Wih_f, Wih_b,
                                       bih_f, bhh_f, bih_b, bhh_b);
    // launch 1: enc L1
    gemm_mma_k<1, 1><<<dim3(4, 256), 256, 66048>>>(
        (const uint16_t*)p_a0h, (const uint16_t*)p_a0l,
        (const uint16_t*)p_w1h, (const uint16_t*)p_w1l,
        b1, nullptr, (uint16_t*)p_a1h, (uint16_t*)p_a1l, 512, 512);
    // launch 2: enc L2
    gemm_mma_k<1, 0><<<dim3(2, 256), 256, 66048>>>(
        (const uint16_t*)p_a1h, (const uint16_t*)p_a1l,
        (const uint16_t*)p_w2h, (const uint16_t*)p_w2l,
        b2, (float*)p_h, nullptr, nullptr, 512, 256);
    // launch 3: fused deltas+feat
    feat_k<<<8192, 256>>>();
    // launch 4: Z = feat @ [Wih_f ; Wih_b]^T + biascat
    gemm_mma_k<0, 0><<<dim3(16, 256), 256, 66048>>>(
        (const uint16_t*)p_fh, (const uint16_t*)p_fl,
        (const uint16_t*)p_wch, (const uint16_t*)p_wcl,
        (const float*)p_bias, (float*)p_Z, nullptr, nullptr, 768, 2048);
    // launch 5: persistent LSTM (ncu -s 5 -c 1 captures this)
    lstm_rec_k<<<128, 256, 66560>>>(Whh_f, Whh_b, h0, c0);
    // launch 6: output assembly
    outk<<<(out_size + 255) / 256, 256>>>(out, out_size);
}